// round 7
// baseline (speedup 1.0000x reference)
#include <cuda_runtime.h>

#define B_ 16
#define N_ 4096
#define D_ 64
#define S_ 1024
#define K_ 32

__device__ int g_fps_idx[B_ * S_];
__device__ float g_xyz_soa[B_ * 3 * N_];   // SoA copy written by fps_kernel

typedef unsigned long long u64t;

__device__ __forceinline__ u64t pack2(float x, float y) {
    u64t r; asm("mov.b64 %0,{%1,%2};" : "=l"(r) : "f"(x), "f"(y)); return r;
}
__device__ __forceinline__ void unpack2(u64t v, float& x, float& y) {
    asm("mov.b64 {%0,%1},%2;" : "=f"(x), "=f"(y) : "l"(v));
}
__device__ __forceinline__ void ffma2(u64t& d, u64t a, u64t b) {
    asm("fma.rn.f32x2 %0,%1,%2,%0;" : "+l"(d) : "l"(a), "l"(b));
}

// ---------------------------------------------------------------------------
// Kernel 1: farthest point sampling (unchanged from R3 — proven ~515us).
// ---------------------------------------------------------------------------
__global__ __launch_bounds__(512) void fps_kernel(const float* __restrict__ xyz,
                                                  float* __restrict__ out_xyz) {
    extern __shared__ float sm[];
    float* xs = sm;
    float* ys = sm + N_;
    float* zs = sm + 2 * N_;
    __shared__ u64t s_slot[8];

    const int b = blockIdx.x, t = threadIdx.x;
    const int lane = t & 31;
    const float* src = xyz + (size_t)b * N_ * 3;
    for (int i = t; i < N_; i += 512) {
        xs[i] = src[3 * i + 0];
        ys[i] = src[3 * i + 1];
        zs[i] = src[3 * i + 2];
    }
    if (t < 8) s_slot[t] = 0ull;
    __syncthreads();
    float* soa = g_xyz_soa + (size_t)b * 3 * N_;
    for (int i = t; i < N_; i += 512) {
        soa[i]          = xs[i];
        soa[N_ + i]     = ys[i];
        soa[2 * N_ + i] = zs[i];
    }

    float px[8], py[8], pz[8], md[8];
#pragma unroll
    for (int j = 0; j < 8; j++) {
        int p = t * 8 + j;
        px[j] = xs[p]; py[j] = ys[p]; pz[j] = zs[p];
        md[j] = 1e10f;
    }

    int last = 0;
#pragma unroll 1
    for (int it = 0; it < S_; ++it) {
        if (t == 0) {
            g_fps_idx[b * S_ + it] = last;
            float* o = out_xyz + ((size_t)b * S_ + it) * 3;
            o[0] = xs[last]; o[1] = ys[last]; o[2] = zs[last];
            s_slot[(it + 2) & 7] = 0ull;
        }
        const float cx = xs[last], cy = ys[last], cz = zs[last];
        float bv = -1.0f;
#pragma unroll
        for (int j = 0; j < 8; j++) {
            float dx = px[j] - cx, dy = py[j] - cy, dz = pz[j] - cz;
            float d = fmaf(dx, dx, fmaf(dy, dy, dz * dz));
            float m = fminf(md[j], d);
            md[j] = m;
            bv = fmaxf(bv, m);
        }
        int bj = 7;
#pragma unroll
        for (int j = 7; j >= 0; j--) if (md[j] == bv) bj = j;
        const int bi = t * 8 + bj;
        float wv = bv;
#pragma unroll
        for (int off = 16; off > 0; off >>= 1)
            wv = fmaxf(wv, __shfl_xor_sync(0xffffffffu, wv, off));
        unsigned msk = __ballot_sync(0xffffffffu, bv == wv);
        const int srcl = __ffs(msk) - 1;
        if (lane == srcl) {
            u64t pk = ((u64t)__float_as_uint(wv) << 32) | (u64t)(4096 - bi);
            atomicMax(&s_slot[it & 7], pk);
        }
        __syncthreads();
        u64t win = s_slot[it & 7];
        last = 4096 - (int)(unsigned)(win & 0xffffffffull);
    }
}

// ---------------------------------------------------------------------------
// f32x2 helper: accumulate 32 channels (16 packed) for one input value.
// ---------------------------------------------------------------------------
__device__ __forceinline__ void acc_fma32p(u64t* acc, const float* w, u64t xx) {
#pragma unroll
    for (int i = 0; i < 8; i++) {
        ulonglong2 wv = *reinterpret_cast<const ulonglong2*>(w + 4 * i);
        ffma2(acc[2 * i + 0], wv.x, xx);
        ffma2(acc[2 * i + 1], wv.y, xx);
    }
}
__device__ __forceinline__ void load32p(u64t* dst, const float* src) {
#pragma unroll
    for (int i = 0; i < 8; i++) {
        ulonglong2 t = *reinterpret_cast<const ulonglong2*>(src + 4 * i);
        dst[2 * i + 0] = t.x;
        dst[2 * i + 1] = t.y;
    }
}

// Shared layout (floats): weights only.
//  0 W1f[67*64]; 4288 b1f[64]; 4352 W2f[64*64]; 8448 b2f[64];
//  8512 W3f[64*128]; 16704 b3f[128]; 16832 grp[4*32] (int) -> 16960 floats
#define SMEM_B_BYTES (16960 * 4)
#define NBX 18
#define SPB 57   // ceil(1024/18)

// ---------------------------------------------------------------------------
// Kernel 2: warp-pair-per-centroid MLP. Lane 2m+hf: neighbor (ws*16+m),
// channel half hf. grid (18,16) = 288 CTAs, 2 CTAs/SM, ~110 regs (no spill).
// ---------------------------------------------------------------------------
__global__ __launch_bounds__(256, 2) void sa_kernel(
    const float* __restrict__ points,
    const float* __restrict__ W0, const float* __restrict__ b0,
    const float* __restrict__ g0, const float* __restrict__ be0,
    const float* __restrict__ m0, const float* __restrict__ v0,
    const float* __restrict__ W1, const float* __restrict__ b1,
    const float* __restrict__ g1, const float* __restrict__ be1,
    const float* __restrict__ m1, const float* __restrict__ v1,
    const float* __restrict__ W2, const float* __restrict__ b2,
    const float* __restrict__ g2, const float* __restrict__ be2,
    const float* __restrict__ m2, const float* __restrict__ v2,
    float* __restrict__ out_pts) {
    extern __shared__ float sm[];
    float* W1f = sm;
    float* b1f = sm + 4288;
    float* W2f = sm + 4352;
    float* b2f = sm + 8448;
    float* W3f = sm + 8512;
    float* b3f = sm + 16704;
    int* grpAll = (int*)(sm + 16832);

    const int b = blockIdx.y, tid = threadIdx.x;
    const float* xs = g_xyz_soa + (size_t)b * 3 * N_;
    const float* ys = xs + N_;
    const float* zs = xs + 2 * N_;

    const int s0   = blockIdx.x * SPB;
    const int send = min(s0 + SPB, S_);

    // zero our output rows (atomicMax target; all results >= 0 after relu)
    {
        float* obase = out_pts + ((size_t)(b * S_ + s0)) * 128;
        const int tot = (send - s0) * 128;
        for (int i = tid; i < tot; i += 256) obase[i] = 0.0f;
    }

    // Fold BN (eval): y = x(W*s) + ((b-m)*s + be), s = g*rsqrt(v+eps)
    for (int i = tid; i < 67 * 64; i += 256) {
        int d = i & 63;
        W1f[i] = W0[i] * (g0[d] * rsqrtf(v0[d] + 1e-5f));
    }
    for (int i = tid; i < 64 * 64; i += 256) {
        int d = i & 63;
        W2f[i] = W1[i] * (g1[d] * rsqrtf(v1[d] + 1e-5f));
    }
    for (int i = tid; i < 64 * 128; i += 256) {
        int d = i & 127;
        W3f[i] = W2[i] * (g2[d] * rsqrtf(v2[d] + 1e-5f));
    }
    if (tid < 64) {
        float s = g0[tid] * rsqrtf(v0[tid] + 1e-5f);
        b1f[tid] = (b0[tid] - m0[tid]) * s + be0[tid];
    }
    if (tid < 64) {
        float s = g1[tid] * rsqrtf(v1[tid] + 1e-5f);
        b2f[tid] = (b1[tid] - m1[tid]) * s + be1[tid];
    }
    if (tid < 128) {
        float s = g2[tid] * rsqrtf(v2[tid] + 1e-5f);
        b3f[tid] = (b2[tid] - m2[tid]) * s + be2[tid];
    }
    __syncthreads();

    const int w = tid >> 5, lane = tid & 31;
    const int rounds = (send - s0 + 3) >> 2;

#pragma unroll 1
    for (int r = 0; r < rounds; ++r) {
        // ---- phase 1: warps 0..3 ball-query centroids r*4+{0..3} ----
        if (w < 4) {
            const int s = s0 + r * 4 + w;
            if (s < send) {
                int* grp = grpAll + w * K_;
                const int fidx = g_fps_idx[b * S_ + s];
                const float cx = __ldg(xs + fidx), cy = __ldg(ys + fidx),
                            cz = __ldg(zs + fidx);
                grp[lane] = -1;
                __syncwarp();
                int cnt = 0;
                for (int base = 0; base < N_ && cnt < K_; base += 32) {
                    const int j = base + lane;
                    float dx = __ldg(xs + j) - cx, dy = __ldg(ys + j) - cy,
                          dz = __ldg(zs + j) - cz;
                    float d2 = dx * dx + dy * dy + dz * dz;
                    bool hit = d2 < 0.04f;   // f32(0.2**2), jax weak-typing
                    unsigned mask = __ballot_sync(0xffffffffu, hit);
                    if (hit) {
                        int pos = cnt + __popc(mask & ((1u << lane) - 1u));
                        if (pos < K_) grp[pos] = j;
                    }
                    cnt += __popc(mask);
                }
            }
        }
        __syncthreads();

        // ---- phase 2: warp pair p = w>>1 runs MLP for centroid r*4+p ----
        const int p  = w >> 1, ws = w & 1;
        const int s  = s0 + r * 4 + p;
        if (s < send) {
            const int m  = lane >> 1, hf = lane & 1;
            const int fidx = g_fps_idx[b * S_ + s];
            const float cx = __ldg(xs + fidx), cy = __ldg(ys + fidx),
                        cz = __ldg(zs + fidx);
            const int ni = grpAll[p * K_ + ws * 16 + m];
            const bool valid = ni >= 0;
            const int pidx = valid ? ni : (N_ - 1);      // torch -1 wrap
            const float in0 = (valid ? __ldg(xs + ni) : 0.0f) - cx;
            const float in1 = (valid ? __ldg(ys + ni) : 0.0f) - cy;
            const float in2 = (valid ? __ldg(zs + ni) : 0.0f) - cz;
            const float4* prow = reinterpret_cast<const float4*>(
                points + ((size_t)b * N_ + pidx) * D_);
            const int ho = hf * 32;   // this lane's channel-half offset

            // ---- layer 1: 67 -> 32 (this half) ----
            u64t hp[16];
            load32p(hp, b1f + ho);
            acc_fma32p(hp, W1f + 0 * 64 + ho, pack2(in0, in0));
            acc_fma32p(hp, W1f + 1 * 64 + ho, pack2(in1, in1));
            acc_fma32p(hp, W1f + 2 * 64 + ho, pack2(in2, in2));
#pragma unroll
            for (int j = 0; j < 16; j++) {
                float4 pv = prow[j];
                acc_fma32p(hp, W1f + (3 + 4 * j + 0) * 64 + ho, pack2(pv.x, pv.x));
                acc_fma32p(hp, W1f + (3 + 4 * j + 1) * 64 + ho, pack2(pv.y, pv.y));
                acc_fma32p(hp, W1f + (3 + 4 * j + 2) * 64 + ho, pack2(pv.z, pv.z));
                acc_fma32p(hp, W1f + (3 + 4 * j + 3) * 64 + ho, pack2(pv.w, pv.w));
            }
            float h[32];
#pragma unroll
            for (int i = 0; i < 16; i++) {
                float a, c2;
                unpack2(hp[i], a, c2);
                h[2 * i + 0] = fmaxf(a, 0.0f);
                h[2 * i + 1] = fmaxf(c2, 0.0f);
            }

            // ---- layer 2: 64 -> 32 (partner half streamed via shfl) ----
            u64t h2p[16];
            load32p(h2p, b2f + ho);
#pragma unroll
            for (int c = 0; c < 64; c++) {
                float mine = h[c & 31];
                float oth  = __shfl_xor_sync(0xffffffffu, mine, 1);
                float x    = ((c >> 5) == hf) ? mine : oth;
                acc_fma32p(h2p, W2f + c * 64 + ho, pack2(x, x));
            }
            float h2[32];
#pragma unroll
            for (int i = 0; i < 16; i++) {
                float a, c2;
                unpack2(h2p[i], a, c2);
                h2[2 * i + 0] = fmaxf(a, 0.0f);
                h2[2 * i + 1] = fmaxf(c2, 0.0f);
            }

            // ---- layer 3: 64 -> 128 in 2 chunks of 64 (32 per lane) ----
            float* outp = out_pts + ((size_t)(b * S_ + s)) * 128;
#pragma unroll 1
            for (int qq = 0; qq < 2; qq++) {
                u64t vp[16];
                load32p(vp, b3f + qq * 64 + ho);
#pragma unroll
                for (int c = 0; c < 64; c++) {
                    float mine = h2[c & 31];
                    float oth  = __shfl_xor_sync(0xffffffffu, mine, 1);
                    float x    = ((c >> 5) == hf) ? mine : oth;
                    acc_fma32p(vp, W3f + c * 128 + qq * 64 + ho, pack2(x, x));
                }
                float v[32];
#pragma unroll
                for (int i = 0; i < 16; i++) {
                    float a, c2;
                    unpack2(vp[i], a, c2);
                    v[2 * i + 0] = fmaxf(a, 0.0f);
                    v[2 * i + 1] = fmaxf(c2, 0.0f);
                }
                // butterfly over m only (xor dists 16,8,4,2): lane 2m+hf ends
                // with v[i] = max over this warp's 16 neighbors of local
                // channel (2m | i).
#pragma unroll
                for (int hh = 16; hh >= 2; hh >>= 1) {
#pragma unroll
                    for (int i = 0; i < hh; i++) {
                        float send2 = (lane & hh) ? v[i] : v[i + hh];
                        float recv = __shfl_xor_sync(0xffffffffu, send2, hh);
                        float keep = (lane & hh) ? v[i + hh] : v[i];
                        v[i] = fmaxf(keep, recv);
                    }
                }
                const int chbase = qq * 64 + ho + (lane & ~1);
                atomicMax((unsigned*)&outp[chbase + 0], __float_as_uint(v[0]));
                atomicMax((unsigned*)&outp[chbase + 1], __float_as_uint(v[1]));
            }
        }
        __syncthreads();   // protect grpAll reuse next round
    }
}

// ---------------------------------------------------------------------------
extern "C" void kernel_launch(void* const* d_in, const int* in_sizes, int n_in,
                              void* d_out, int out_size) {
    const float* xyz    = (const float*)d_in[0];
    const float* points = (const float*)d_in[1];
    const float* W0  = (const float*)d_in[2];
    const float* b0  = (const float*)d_in[3];
    const float* g0  = (const float*)d_in[4];
    const float* be0 = (const float*)d_in[5];
    const float* m0  = (const float*)d_in[6];
    const float* v0  = (const float*)d_in[7];
    const float* W1  = (const float*)d_in[8];
    const float* b1  = (const float*)d_in[9];
    const float* g1  = (const float*)d_in[10];
    const float* be1 = (const float*)d_in[11];
    const float* m1  = (const float*)d_in[12];
    const float* v1  = (const float*)d_in[13];
    const float* W2  = (const float*)d_in[14];
    const float* b2  = (const float*)d_in[15];
    const float* g2  = (const float*)d_in[16];
    const float* be2 = (const float*)d_in[17];
    const float* m2  = (const float*)d_in[18];
    const float* v2  = (const float*)d_in[19];

    float* out_xyz = (float*)d_out;                       // (B,S,3)
    float* out_pts = (float*)d_out + (size_t)B_ * S_ * 3; // (B,S,128)

    cudaFuncSetAttribute(fps_kernel, cudaFuncAttributeMaxDynamicSharedMemorySize,
                         3 * N_ * 4);
    cudaFuncSetAttribute(sa_kernel, cudaFuncAttributeMaxDynamicSharedMemorySize,
                         SMEM_B_BYTES);

    fps_kernel<<<B_, 512, 3 * N_ * 4>>>(xyz, out_xyz);
    sa_kernel<<<dim3(NBX, B_), 256, SMEM_B_BYTES>>>(
        points,
        W0, b0, g0, be0, m0, v0,
        W1, b1, g1, be1, m1, v1,
        W2, b2, g2, be2, m2, v2,
        out_pts);
}

// round 9
// speedup vs baseline: 1.3502x; 1.3502x over previous
#include <cuda_runtime.h>

#define B_ 16
#define N_ 4096
#define D_ 64
#define S_ 1024
#define K_ 32

__device__ int g_fps_idx[B_ * S_];

typedef unsigned long long u64t;

__device__ __forceinline__ u64t pack2(float x, float y) {
    u64t r; asm("mov.b64 %0,{%1,%2};" : "=l"(r) : "f"(x), "f"(y)); return r;
}
__device__ __forceinline__ void unpack2(u64t v, float& x, float& y) {
    asm("mov.b64 {%0,%1},%2;" : "=f"(x), "=f"(y) : "l"(v));
}
__device__ __forceinline__ void ffma2(u64t& d, u64t a, u64t b) {
    asm("fma.rn.f32x2 %0,%1,%2,%0;" : "+l"(d) : "l"(a), "l"(b));
}

// ---------------------------------------------------------------------------
// Kernel 1: farthest point sampling. 512 threads, 8 pts/thread.
// Argmax: per-point packed u64 (dist_bits<<32 | 4096-idx) -> in-warp 5-level
// butterfly max -> lane0 STS -> one barrier -> every warp redundantly
// butterfly-reduces the 16 partials (no atomics, no 2nd barrier).
// ---------------------------------------------------------------------------
__global__ __launch_bounds__(512) void fps_kernel(const float* __restrict__ xyz,
                                                  float* __restrict__ out_xyz) {
    extern __shared__ float sm[];
    float* xs = sm;
    float* ys = sm + N_;
    float* zs = sm + 2 * N_;
    __shared__ u64t s_warp[2][16];

    const int b = blockIdx.x, t = threadIdx.x;
    const int warp = t >> 5, lane = t & 31;
    const float* src = xyz + (size_t)b * N_ * 3;
    for (int i = t; i < N_; i += 512) {
        xs[i] = src[3 * i + 0];
        ys[i] = src[3 * i + 1];
        zs[i] = src[3 * i + 2];
    }
    __syncthreads();

    float px[8], py[8], pz[8], md[8];
#pragma unroll
    for (int j = 0; j < 8; j++) {
        int p = t * 8 + j;
        px[j] = xs[p]; py[j] = ys[p]; pz[j] = zs[p];
        md[j] = 1e10f;
    }

    int last = 0;
#pragma unroll 1
    for (int it = 0; it < S_; ++it) {
        if (t == 0) {
            g_fps_idx[b * S_ + it] = last;
            float* o = out_xyz + ((size_t)b * S_ + it) * 3;
            o[0] = xs[last]; o[1] = ys[last]; o[2] = zs[last];
        }
        const float cx = xs[last], cy = ys[last], cz = zs[last];
        u64t pk = 0ull;
#pragma unroll
        for (int j = 0; j < 8; j++) {
            float dx = px[j] - cx, dy = py[j] - cy, dz = pz[j] - cz;
            float d = fmaf(dx, dx, fmaf(dy, dy, dz * dz));
            float m = fminf(md[j], d);
            md[j] = m;
            // dist >= 0 so float bits are monotonic; ties -> larger (4096-idx)
            // = smaller idx, matching jnp.argmax first-occurrence.
            u64t pj = ((u64t)__float_as_uint(m) << 32) | (u64t)(4096 - (t * 8 + j));
            pk = (pj > pk) ? pj : pk;
        }
#pragma unroll
        for (int off = 16; off > 0; off >>= 1) {
            u64t o = __shfl_xor_sync(0xffffffffu, pk, off);
            pk = (o > pk) ? o : pk;
        }
        const int buf = it & 1;
        if (lane == 0) s_warp[buf][warp] = pk;
        __syncthreads();
        u64t v = s_warp[buf][lane & 15];
#pragma unroll
        for (int off = 8; off > 0; off >>= 1) {
            u64t o = __shfl_xor_sync(0xffffffffu, v, off);
            v = (o > v) ? o : v;
        }
        last = 4096 - (int)(unsigned)(v & 0xffffffffull);
    }
}

// ---------------------------------------------------------------------------
// Packed f32x2 helpers for the MLP.
// ---------------------------------------------------------------------------
__device__ __forceinline__ void acc_fma64p(u64t* acc, const float* w, u64t xx) {
#pragma unroll
    for (int i = 0; i < 16; i++) {
        ulonglong2 wv = *reinterpret_cast<const ulonglong2*>(w + 4 * i);
        ffma2(acc[2 * i + 0], wv.x, xx);
        ffma2(acc[2 * i + 1], wv.y, xx);
    }
}
__device__ __forceinline__ void acc_fma32p(u64t* acc, const float* w, u64t xx) {
#pragma unroll
    for (int i = 0; i < 8; i++) {
        ulonglong2 wv = *reinterpret_cast<const ulonglong2*>(w + 4 * i);
        ffma2(acc[2 * i + 0], wv.x, xx);
        ffma2(acc[2 * i + 1], wv.y, xx);
    }
}
__device__ __forceinline__ void load64p(u64t* dst, const float* src) {
#pragma unroll
    for (int i = 0; i < 16; i++) {
        ulonglong2 t = *reinterpret_cast<const ulonglong2*>(src + 4 * i);
        dst[2 * i + 0] = t.x;
        dst[2 * i + 1] = t.y;
    }
}
__device__ __forceinline__ void load32p(u64t* dst, const float* src) {
#pragma unroll
    for (int i = 0; i < 8; i++) {
        ulonglong2 t = *reinterpret_cast<const ulonglong2*>(src + 4 * i);
        dst[2 * i + 0] = t.x;
        dst[2 * i + 1] = t.y;
    }
}

// Shared layout (floats):
//  0      xs[4096], 4096 ys, 8192 zs
//  12288  W1f[67*64]   16576 b1f[64]
//  16640  W2f[64*64]   20736 b2f[64]
//  20800  W3f[64*128]  28992 b3f[128]
//  29120  grp[8*32] (int)            -> total 29376 floats = 117504 bytes
#define SMEM_B_BYTES (29376 * 4)
#define SPB 114   // centroids per block (9 blocks * 114 >= 1024)

// ---------------------------------------------------------------------------
// Kernel 2 (R2-proven 736us): ball query + gather + folded-BN MLP (f32x2) +
// max-pool. grid (9, 16) = 144 CTAs -> single wave at 1 CTA/SM.
// ---------------------------------------------------------------------------
__global__ __launch_bounds__(256) void sa_kernel(
    const float* __restrict__ xyz, const float* __restrict__ points,
    const float* __restrict__ W0, const float* __restrict__ b0,
    const float* __restrict__ g0, const float* __restrict__ be0,
    const float* __restrict__ m0, const float* __restrict__ v0,
    const float* __restrict__ W1, const float* __restrict__ b1,
    const float* __restrict__ g1, const float* __restrict__ be1,
    const float* __restrict__ m1, const float* __restrict__ v1,
    const float* __restrict__ W2, const float* __restrict__ b2,
    const float* __restrict__ g2, const float* __restrict__ be2,
    const float* __restrict__ m2, const float* __restrict__ v2,
    float* __restrict__ out_pts) {
    extern __shared__ float sm[];
    float* xs  = sm;
    float* ys  = sm + 4096;
    float* zs  = sm + 8192;
    float* W1f = sm + 12288;
    float* b1f = sm + 16576;
    float* W2f = sm + 16640;
    float* b2f = sm + 20736;
    float* W3f = sm + 20800;
    float* b3f = sm + 28992;
    int* grpAll = (int*)(sm + 29120);

    const int b = blockIdx.y, tid = threadIdx.x;

    const float* xb = xyz + (size_t)b * N_ * 3;
    for (int i = tid; i < N_; i += 256) {
        xs[i] = xb[3 * i + 0];
        ys[i] = xb[3 * i + 1];
        zs[i] = xb[3 * i + 2];
    }
    // Fold BN (eval): y = x(W*s) + ((b-m)*s + be), s = g*rsqrt(v+eps)
    for (int i = tid; i < 67 * 64; i += 256) {
        int d = i & 63;
        W1f[i] = W0[i] * (g0[d] * rsqrtf(v0[d] + 1e-5f));
    }
    for (int i = tid; i < 64 * 64; i += 256) {
        int d = i & 63;
        W2f[i] = W1[i] * (g1[d] * rsqrtf(v1[d] + 1e-5f));
    }
    for (int i = tid; i < 64 * 128; i += 256) {
        int d = i & 127;
        W3f[i] = W2[i] * (g2[d] * rsqrtf(v2[d] + 1e-5f));
    }
    if (tid < 64) {
        float s = g0[tid] * rsqrtf(v0[tid] + 1e-5f);
        b1f[tid] = (b0[tid] - m0[tid]) * s + be0[tid];
    }
    if (tid < 64) {
        float s = g1[tid] * rsqrtf(v1[tid] + 1e-5f);
        b2f[tid] = (b1[tid] - m1[tid]) * s + be1[tid];
    }
    if (tid < 128) {
        float s = g2[tid] * rsqrtf(v2[tid] + 1e-5f);
        b3f[tid] = (b2[tid] - m2[tid]) * s + be2[tid];
    }
    __syncthreads();

    const int w = tid >> 5, lane = tid & 31;
    int* grp = grpAll + w * K_;

    const int s0   = blockIdx.x * SPB;
    const int send = min(s0 + SPB, S_);

#pragma unroll 1
    for (int s = s0 + w; s < send; s += 8) {
        const int fidx = g_fps_idx[b * S_ + s];
        const float cx = xs[fidx], cy = ys[fidx], cz = zs[fidx];

        // ---- ball query: first-K in index order, ballot+popc, early exit ----
        grp[lane] = -1;
        __syncwarp();
        int cnt = 0;
        for (int base = 0; base < N_ && cnt < K_; base += 32) {
            const int j = base + lane;
            float dx = xs[j] - cx, dy = ys[j] - cy, dz = zs[j] - cz;
            float d2 = dx * dx + dy * dy + dz * dz;
            bool hit = d2 < 0.04f;   // f32(0.2**2), matches jax weak-typing
            unsigned mask = __ballot_sync(0xffffffffu, hit);
            if (hit) {
                int pos = cnt + __popc(mask & ((1u << lane) - 1u));
                if (pos < K_) grp[pos] = j;
            }
            cnt += __popc(mask);
        }
        __syncwarp();
        const int ni = grp[lane];
        const bool valid = ni >= 0;
        const int pidx = valid ? ni : (N_ - 1);          // torch -1 wrap for points
        const float in0 = (valid ? xs[ni] : 0.0f) - cx;  // grouped_xyz zeroed if pad
        const float in1 = (valid ? ys[ni] : 0.0f) - cy;
        const float in2 = (valid ? zs[ni] : 0.0f) - cz;
        const float4* prow =
            reinterpret_cast<const float4*>(points + ((size_t)b * N_ + pidx) * D_);

        // ---- layer 1: 67 -> 64 (packed f32x2 accumulators) ----
        u64t hp[32];
        load64p(hp, b1f);
        acc_fma64p(hp, W1f + 0 * 64, pack2(in0, in0));
        acc_fma64p(hp, W1f + 1 * 64, pack2(in1, in1));
        acc_fma64p(hp, W1f + 2 * 64, pack2(in2, in2));
#pragma unroll
        for (int j = 0; j < 16; j++) {
            float4 p = prow[j];
            acc_fma64p(hp, W1f + (3 + 4 * j + 0) * 64, pack2(p.x, p.x));
            acc_fma64p(hp, W1f + (3 + 4 * j + 1) * 64, pack2(p.y, p.y));
            acc_fma64p(hp, W1f + (3 + 4 * j + 2) * 64, pack2(p.z, p.z));
            acc_fma64p(hp, W1f + (3 + 4 * j + 3) * 64, pack2(p.w, p.w));
        }
        float h[64];
#pragma unroll
        for (int i = 0; i < 32; i++) {
            float a, c2;
            unpack2(hp[i], a, c2);
            h[2 * i + 0] = fmaxf(a, 0.0f);
            h[2 * i + 1] = fmaxf(c2, 0.0f);
        }

        // ---- layer 2: 64 -> 64 ----
        u64t h2p[32];
        load64p(h2p, b2f);
#pragma unroll
        for (int c = 0; c < 64; c++) acc_fma64p(h2p, W2f + c * 64, pack2(h[c], h[c]));
        float h2[64];
#pragma unroll
        for (int i = 0; i < 32; i++) {
            float a, c2;
            unpack2(h2p[i], a, c2);
            h2[2 * i + 0] = fmaxf(a, 0.0f);
            h2[2 * i + 1] = fmaxf(c2, 0.0f);
        }

        // ---- layer 3: 64 -> 128 in 4 chunks of 32, fused max over K ----
        float* outp = out_pts + ((size_t)(b * S_ + s)) * 128;
#pragma unroll 1
        for (int q = 0; q < 4; q++) {
            u64t vp[16];
            load32p(vp, b3f + q * 32);
#pragma unroll
            for (int c = 0; c < 64; c++)
                acc_fma32p(vp, W3f + c * 128 + q * 32, pack2(h2[c], h2[c]));
            float v[32];
#pragma unroll
            for (int i = 0; i < 16; i++) {
                float a, c2;
                unpack2(vp[i], a, c2);
                v[2 * i + 0] = fmaxf(a, 0.0f);
                v[2 * i + 1] = fmaxf(c2, 0.0f);
            }
            // transpose-reduce: lane l ends with max over lanes of channel q*32+l
#pragma unroll
            for (int hh = 16; hh >= 1; hh >>= 1) {
#pragma unroll
                for (int i = 0; i < hh; i++) {
                    float send2 = (lane & hh) ? v[i] : v[i + hh];
                    float recv = __shfl_xor_sync(0xffffffffu, send2, hh);
                    float keep = (lane & hh) ? v[i + hh] : v[i];
                    v[i] = fmaxf(keep, recv);
                }
            }
            outp[q * 32 + lane] = v[0];
        }
    }
}

// ---------------------------------------------------------------------------
extern "C" void kernel_launch(void* const* d_in, const int* in_sizes, int n_in,
                              void* d_out, int out_size) {
    const float* xyz    = (const float*)d_in[0];
    const float* points = (const float*)d_in[1];
    const float* W0  = (const float*)d_in[2];
    const float* b0  = (const float*)d_in[3];
    const float* g0  = (const float*)d_in[4];
    const float* be0 = (const float*)d_in[5];
    const float* m0  = (const float*)d_in[6];
    const float* v0  = (const float*)d_in[7];
    const float* W1  = (const float*)d_in[8];
    const float* b1  = (const float*)d_in[9];
    const float* g1  = (const float*)d_in[10];
    const float* be1 = (const float*)d_in[11];
    const float* m1  = (const float*)d_in[12];
    const float* v1  = (const float*)d_in[13];
    const float* W2  = (const float*)d_in[14];
    const float* b2  = (const float*)d_in[15];
    const float* g2  = (const float*)d_in[16];
    const float* be2 = (const float*)d_in[17];
    const float* m2  = (const float*)d_in[18];
    const float* v2  = (const float*)d_in[19];

    float* out_xyz = (float*)d_out;                       // (B,S,3)
    float* out_pts = (float*)d_out + (size_t)B_ * S_ * 3; // (B,S,128)

    cudaFuncSetAttribute(fps_kernel, cudaFuncAttributeMaxDynamicSharedMemorySize,
                         3 * N_ * 4);
    cudaFuncSetAttribute(sa_kernel, cudaFuncAttributeMaxDynamicSharedMemorySize,
                         SMEM_B_BYTES);

    fps_kernel<<<B_, 512, 3 * N_ * 4>>>(xyz, out_xyz);
    sa_kernel<<<dim3(9, B_), 256, SMEM_B_BYTES>>>(
        xyz, points,
        W0, b0, g0, be0, m0, v0,
        W1, b1, g1, be1, m1, v1,
        W2, b2, g2, be2, m2, v2,
        out_pts);
}